// round 7
// baseline (speedup 1.0000x reference)
#include <cuda_runtime.h>
#include <cuda_bf16.h>
#include <math.h>

typedef unsigned long long ull;

static const int NN = 100000;
static const int EE = 1600000;

#define EPI_RELU 1
#define EPI_BIAS 2
#define EPI_ADDC 4

// ----------------------------------------------------------------------------
// Scratch (device globals; no allocation allowed)
// ----------------------------------------------------------------------------
__device__ float g_h1[100000 * 512];
__device__ float g_h2[100000 * 64];
__device__ float g_logits[100000 * 64];
__device__ float g_tp[100000 * 64];
__device__ float g_xh[100000 * 128];
__device__ float g_tmp[100000 * 128];
__device__ float g_a[100000 * 128];
__device__ float g_pv[100000 * 128];
__device__ float g_agg[100000 * 128];
__device__ float g_pos[100000 * 3];
__device__ float g_ew[1600000];
__device__ float g_ews[1600000];
__device__ float g_parsing[64 * 64];
__device__ int   g_cnt[100000];
__device__ int   g_off[100001];
__device__ int   g_cur[100000];
__device__ int   g_csrc[1600000];
__device__ int   g_ceid[1600000];
__device__ double g_sum2[2];
__device__ float g_ms[2];
__device__ int   g_is64;

// ----------------------------------------------------------------------------
// Edge index loader (handles int64 or int32 edge_index)
// ----------------------------------------------------------------------------
__device__ __forceinline__ int load_edge(const void* ei, int which, int e) {
    if (g_is64)
        return (int)reinterpret_cast<const long long*>(ei)[(size_t)which * EE + e];
    return reinterpret_cast<const int*>(ei)[(size_t)which * EE + e];
}

__global__ void detect_kernel(const unsigned long long* p) {
    __shared__ int bad;
    if (threadIdx.x == 0) bad = 0;
    __syncthreads();
    if (p[threadIdx.x] >= 100000ULL) atomicAdd(&bad, 1);
    __syncthreads();
    if (threadIdx.x == 0) g_is64 = (bad == 0) ? 1 : 0;
}

// ----------------------------------------------------------------------------
// Register-tiled SGEMM with packed fp32x2 FMA (fma.rn.f32x2, sm_100+)
// C[M,Nt] = epilogue(A[M,K] @ B[K,Nt])
// TM=TN=8 per thread. Accumulators are f32x2 pairs along N.
// ----------------------------------------------------------------------------
template <int BM, int BN, int BK, int EPI>
__global__ void __launch_bounds__((BM / 8) * (BN / 8))
sgemm_f2(const float* __restrict__ A, const float* __restrict__ B,
         const float* __restrict__ bias, const float* __restrict__ Cadd,
         float* __restrict__ Cout, int M, int K, int Nt) {
    constexpr int TM = 8, TN = 8;
    constexpr int NTX = BN / TN;
    constexpr int THREADS = (BM / TM) * NTX;
    __shared__ float As[BK][BM];
    __shared__ float Bs[BK][BN];

    const int tid = threadIdx.x;
    const int tx = tid % NTX;
    const int ty = tid / NTX;
    const int rowBase = blockIdx.x * BM;
    const int colBase = blockIdx.y * BN;

    ull acc[TM][TN / 2];
#pragma unroll
    for (int i = 0; i < TM; i++)
#pragma unroll
        for (int j = 0; j < TN / 2; j++) acc[i][j] = 0ULL;

    constexpr int SEGS = BK / 4;
    constexpr int A_IT = (BM * BK / 4) / THREADS;
    constexpr int BSEG = BN / 4;
    constexpr int B_IT = (BK * BN / 4) / THREADS;

    for (int k0 = 0; k0 < K; k0 += BK) {
#pragma unroll
        for (int i = 0; i < A_IT; i++) {
            int lin = tid + i * THREADS;
            int r = lin / SEGS, s = lin % SEGS;
            int grow = rowBase + r;
            float4 v = make_float4(0.f, 0.f, 0.f, 0.f);
            if (grow < M)
                v = *reinterpret_cast<const float4*>(A + (size_t)grow * K + k0 + s * 4);
            As[s * 4 + 0][r] = v.x;
            As[s * 4 + 1][r] = v.y;
            As[s * 4 + 2][r] = v.z;
            As[s * 4 + 3][r] = v.w;
        }
#pragma unroll
        for (int i = 0; i < B_IT; i++) {
            int lin = tid + i * THREADS;
            int r = lin / BSEG, c = lin % BSEG;
            *reinterpret_cast<float4*>(&Bs[r][c * 4]) =
                *reinterpret_cast<const float4*>(B + (size_t)(k0 + r) * Nt + colBase + c * 4);
        }
        __syncthreads();
#pragma unroll
        for (int k = 0; k < BK; k++) {
            float4 a0 = *reinterpret_cast<const float4*>(&As[k][ty * TM]);
            float4 a1 = *reinterpret_cast<const float4*>(&As[k][ty * TM + 4]);
            const ull* bp = reinterpret_cast<const ull*>(&Bs[k][tx * TN]);
            ull b0 = bp[0], b1 = bp[1], b2 = bp[2], b3 = bp[3];
            float av[8] = {a0.x, a0.y, a0.z, a0.w, a1.x, a1.y, a1.z, a1.w};
#pragma unroll
            for (int i = 0; i < TM; i++) {
                ull ap;
                asm("mov.b64 %0, {%1, %1};" : "=l"(ap) : "f"(av[i]));
                asm("fma.rn.f32x2 %0, %1, %2, %0;" : "+l"(acc[i][0]) : "l"(ap), "l"(b0));
                asm("fma.rn.f32x2 %0, %1, %2, %0;" : "+l"(acc[i][1]) : "l"(ap), "l"(b1));
                asm("fma.rn.f32x2 %0, %1, %2, %0;" : "+l"(acc[i][2]) : "l"(ap), "l"(b2));
                asm("fma.rn.f32x2 %0, %1, %2, %0;" : "+l"(acc[i][3]) : "l"(ap), "l"(b3));
            }
        }
        __syncthreads();
    }

    const int gcol = colBase + tx * TN;
    float bv[TN];
    if (EPI & EPI_BIAS) {
        float4 t0 = *reinterpret_cast<const float4*>(bias + gcol);
        float4 t1 = *reinterpret_cast<const float4*>(bias + gcol + 4);
        bv[0] = t0.x; bv[1] = t0.y; bv[2] = t0.z; bv[3] = t0.w;
        bv[4] = t1.x; bv[5] = t1.y; bv[6] = t1.z; bv[7] = t1.w;
    } else {
#pragma unroll
        for (int j = 0; j < TN; j++) bv[j] = 0.f;
    }
#pragma unroll
    for (int i = 0; i < TM; i++) {
        int grow = rowBase + ty * TM + i;
        if (grow >= M) continue;
        float o[TN];
#pragma unroll
        for (int j = 0; j < TN / 2; j++) {
            float lo, hi;
            asm("mov.b64 {%0, %1}, %2;" : "=f"(lo), "=f"(hi) : "l"(acc[i][j]));
            o[2 * j] = lo + bv[2 * j];
            o[2 * j + 1] = hi + bv[2 * j + 1];
        }
        if (EPI & EPI_ADDC) {
            float4 c0 = *reinterpret_cast<const float4*>(Cadd + (size_t)grow * Nt + gcol);
            float4 c1 = *reinterpret_cast<const float4*>(Cadd + (size_t)grow * Nt + gcol + 4);
            o[0] += c0.x; o[1] += c0.y; o[2] += c0.z; o[3] += c0.w;
            o[4] += c1.x; o[5] += c1.y; o[6] += c1.z; o[7] += c1.w;
        }
        if (EPI & EPI_RELU) {
#pragma unroll
            for (int j = 0; j < TN; j++) o[j] = fmaxf(o[j], 0.f);
        }
        *reinterpret_cast<float4*>(Cout + (size_t)grow * Nt + gcol) =
            make_float4(o[0], o[1], o[2], o[3]);
        *reinterpret_cast<float4*>(Cout + (size_t)grow * Nt + gcol + 4) =
            make_float4(o[4], o[5], o[6], o[7]);
    }
}

// ----------------------------------------------------------------------------
// parsing = relu(2 * P0)
// ----------------------------------------------------------------------------
__global__ void parsing_kernel(const float* __restrict__ P0) {
    int i = blockIdx.x * blockDim.x + threadIdx.x;
    if (i < 64 * 64) g_parsing[i] = fmaxf(0.f, 2.0f * P0[i]);
}

// ----------------------------------------------------------------------------
// ew[e] = dot64(logits[src], tp[dst]); accumulate sum & sumsq (double)
// One warp per edge; blockDim = 256 (8 warps).
// ----------------------------------------------------------------------------
__global__ void ew_kernel(const void* __restrict__ ei, const float* __restrict__ logits,
                          const float* __restrict__ tp, float* __restrict__ ew,
                          double* __restrict__ sum2) {
    int gw = (blockIdx.x * blockDim.x + threadIdx.x) >> 5;
    int lane = threadIdx.x & 31;
    int wib = threadIdx.x >> 5;
    __shared__ float sv[8], sq[8];
    float val = 0.f;
    bool valid = gw < EE;
    if (valid) {
        int s = load_edge(ei, 0, gw);
        int d = load_edge(ei, 1, gw);
        float2 la = reinterpret_cast<const float2*>(logits + (size_t)s * 64)[lane];
        float2 tb = reinterpret_cast<const float2*>(tp + (size_t)d * 64)[lane];
        val = la.x * tb.x + la.y * tb.y;
#pragma unroll
        for (int o = 16; o; o >>= 1) val += __shfl_down_sync(0xffffffffu, val, o);
        if (lane == 0) ew[gw] = val;
    }
    if (lane == 0) {
        sv[wib] = valid ? val : 0.f;
        sq[wib] = valid ? val * val : 0.f;
    }
    __syncthreads();
    if (threadIdx.x == 0) {
        double s = 0, q = 0;
#pragma unroll
        for (int i = 0; i < 8; i++) { s += (double)sv[i]; q += (double)sq[i]; }
        atomicAdd(sum2 + 0, s);
        atomicAdd(sum2 + 1, q);
    }
}

__global__ void finalize_kernel(const double* __restrict__ sum2, float* __restrict__ ms) {
    double s = sum2[0], q = sum2[1];
    double Ed = (double)EE;
    double mean = s / Ed;
    double var = (q - s * s / Ed) / (Ed - 1.0);
    ms[0] = (float)mean;
    ms[1] = (float)sqrt(1e-4 / var);
}

// ----------------------------------------------------------------------------
// CSR build
// ----------------------------------------------------------------------------
__global__ void count_kernel(const void* __restrict__ ei, int* __restrict__ cnt) {
    int e = blockIdx.x * blockDim.x + threadIdx.x;
    if (e >= EE) return;
    atomicAdd(&cnt[load_edge(ei, 1, e)], 1);
}

__global__ void scan_kernel(const int* __restrict__ cnt, int* __restrict__ off,
                            int* __restrict__ cur) {
    __shared__ int sh[1024];
    const int T = 1024;
    int tid = threadIdx.x;
    const int CH = (NN + T - 1) / T;  // 98
    int b0 = tid * CH;
    int loc = 0;
    for (int i = 0; i < CH; i++) {
        int idx = b0 + i;
        if (idx < NN) loc += cnt[idx];
    }
    sh[tid] = loc;
    __syncthreads();
    for (int o = 1; o < T; o <<= 1) {
        int t = (tid >= o) ? sh[tid - o] : 0;
        __syncthreads();
        sh[tid] += t;
        __syncthreads();
    }
    int excl = sh[tid] - loc;
    int run = excl;
    for (int i = 0; i < CH; i++) {
        int idx = b0 + i;
        if (idx < NN) {
            off[idx] = run;
            cur[idx] = run;
            run += cnt[idx];
        }
    }
    if (tid == T - 1) off[NN] = EE;
}

__global__ void scatter_kernel(const void* __restrict__ ei, int* __restrict__ cur,
                               int* __restrict__ csrc, int* __restrict__ ceid) {
    int e = blockIdx.x * blockDim.x + threadIdx.x;
    if (e >= EE) return;
    int d = load_edge(ei, 1, e);
    int p = atomicAdd(&cur[d], 1);
    csrc[p] = load_edge(ei, 0, e);
    ceid[p] = e;
}

// ews[i] = (ew[ceid[i]] - mean) * scale + 1
__global__ void ewperm_kernel(const float* __restrict__ ew, const int* __restrict__ ceid,
                              const float* __restrict__ ms, float* __restrict__ ews) {
    int i = blockIdx.x * blockDim.x + threadIdx.x;
    if (i >= EE) return;
    ews[i] = (__ldg(ew + __ldg(ceid + i)) - ms[0]) * ms[1] + 1.0f;
}

// ----------------------------------------------------------------------------
// pos = t2 @ Wp2 + bp2 (K=128, Nout=3). One warp per node.
// ----------------------------------------------------------------------------
__global__ void pos_kernel(const float* __restrict__ t2, const float* __restrict__ Wp2,
                           const float* __restrict__ bp2, float* __restrict__ pos) {
    __shared__ float sw[384];
    for (int i = threadIdx.x; i < 384; i += blockDim.x) sw[i] = Wp2[i];
    __syncthreads();
    int gw = (blockIdx.x * blockDim.x + threadIdx.x) >> 5;
    int lane = threadIdx.x & 31;
    if (gw >= NN) return;
    float4 v = *reinterpret_cast<const float4*>(t2 + (size_t)gw * 128 + lane * 4);
    int k0 = lane * 4;
    float p0 = v.x * sw[k0 * 3 + 0] + v.y * sw[(k0 + 1) * 3 + 0] +
               v.z * sw[(k0 + 2) * 3 + 0] + v.w * sw[(k0 + 3) * 3 + 0];
    float p1 = v.x * sw[k0 * 3 + 1] + v.y * sw[(k0 + 1) * 3 + 1] +
               v.z * sw[(k0 + 2) * 3 + 1] + v.w * sw[(k0 + 3) * 3 + 1];
    float p2 = v.x * sw[k0 * 3 + 2] + v.y * sw[(k0 + 1) * 3 + 2] +
               v.z * sw[(k0 + 2) * 3 + 2] + v.w * sw[(k0 + 3) * 3 + 2];
#pragma unroll
    for (int o = 16; o; o >>= 1) {
        p0 += __shfl_down_sync(0xffffffffu, p0, o);
        p1 += __shfl_down_sync(0xffffffffu, p1, o);
        p2 += __shfl_down_sync(0xffffffffu, p2, o);
    }
    if (lane == 0) {
        pos[gw * 3 + 0] = p0 + __ldg(bp2 + 0);
        pos[gw * 3 + 1] = p1 + __ldg(bp2 + 1);
        pos[gw * 3 + 2] = p2 + __ldg(bp2 + 2);
    }
}

// pv = pos @ WlB (K=3, Nout=128)
__global__ void pv_kernel(const float* __restrict__ pos, const float* __restrict__ WlB,
                          float* __restrict__ pv) {
    int idx = blockIdx.x * blockDim.x + threadIdx.x;
    if (idx >= NN * 128) return;
    int n = idx >> 7, j = idx & 127;
    float p0 = __ldg(pos + n * 3 + 0);
    float p1 = __ldg(pos + n * 3 + 1);
    float p2 = __ldg(pos + n * 3 + 2);
    pv[idx] = p0 * __ldg(WlB + j) + p1 * __ldg(WlB + 128 + j) + p2 * __ldg(WlB + 256 + j);
}

// ----------------------------------------------------------------------------
// Aggregation: warp per dst node; agg[n] = max_e ((a[src]-pv[n]) * ew_s[e]); empty -> 0
// ----------------------------------------------------------------------------
__global__ void agg_kernel(const int* __restrict__ off, const int* __restrict__ csrc,
                           const float* __restrict__ ews, const float* __restrict__ a,
                           const float* __restrict__ pv, float* __restrict__ agg) {
    int gw = (blockIdx.x * blockDim.x + threadIdx.x) >> 5;
    int lane = threadIdx.x & 31;
    if (gw >= NN) return;
    int beg = __ldg(off + gw), end = __ldg(off + gw + 1);
    float4 pvd = *reinterpret_cast<const float4*>(pv + (size_t)gw * 128 + lane * 4);
    float mx0 = -INFINITY, mx1 = -INFINITY, mx2 = -INFINITY, mx3 = -INFINITY;
    int e = beg;
    int sN = 0;
    float wN = 0.f;
    if (e < end) { sN = __ldg(csrc + e); wN = __ldg(ews + e); }
    for (; e < end; e++) {
        int s = sN;
        float w = wN;
        if (e + 1 < end) { sN = __ldg(csrc + e + 1); wN = __ldg(ews + e + 1); }
        float4 av = *reinterpret_cast<const float4*>(a + (size_t)s * 128 + lane * 4);
        mx0 = fmaxf(mx0, (av.x - pvd.x) * w);
        mx1 = fmaxf(mx1, (av.y - pvd.y) * w);
        mx2 = fmaxf(mx2, (av.z - pvd.z) * w);
        mx3 = fmaxf(mx3, (av.w - pvd.w) * w);
    }
    float4 r = (beg == end) ? make_float4(0.f, 0.f, 0.f, 0.f)
                            : make_float4(mx0, mx1, mx2, mx3);
    *reinterpret_cast<float4*>(agg + (size_t)gw * 128 + lane * 4) = r;
}

// ----------------------------------------------------------------------------
// Host launcher
// ----------------------------------------------------------------------------
extern "C" void kernel_launch(void* const* d_in, const int* in_sizes, int n_in,
                              void* d_out, int out_size) {
    const float* x   = (const float*)d_in[0];
    const void*  ei  = d_in[1];
    const float* Wm1 = (const float*)d_in[2];  const float* bm1 = (const float*)d_in[3];
    const float* Wm2 = (const float*)d_in[4];  const float* bm2 = (const float*)d_in[5];
    const float* Wm3 = (const float*)d_in[6];  const float* bm3 = (const float*)d_in[7];
    const float* P0  = (const float*)d_in[8];
    const float* Wi1 = (const float*)d_in[9];  const float* bi1 = (const float*)d_in[10];
    const float* Wi2 = (const float*)d_in[11]; const float* bi2 = (const float*)d_in[12];
    const float* Wp1 = (const float*)d_in[13]; const float* bp1 = (const float*)d_in[14];
    const float* Wp2 = (const float*)d_in[15]; const float* bp2 = (const float*)d_in[16];
    const float* Wl  = (const float*)d_in[17]; const float* bl  = (const float*)d_in[18];
    const float* Wg  = (const float*)d_in[19]; const float* bg  = (const float*)d_in[20];
    const float* Wf  = (const float*)d_in[21]; const float* bf  = (const float*)d_in[22];
    float* out = (float*)d_out;

    float *h1, *h2, *logits, *tp, *xh, *tmp, *a, *pv, *agg, *pos, *ew, *ews, *parsing, *ms;
    int *cnt, *off, *cur, *csrc, *ceid;
    double* sum2;
    cudaGetSymbolAddress((void**)&h1, g_h1);
    cudaGetSymbolAddress((void**)&h2, g_h2);
    cudaGetSymbolAddress((void**)&logits, g_logits);
    cudaGetSymbolAddress((void**)&tp, g_tp);
    cudaGetSymbolAddress((void**)&xh, g_xh);
    cudaGetSymbolAddress((void**)&tmp, g_tmp);
    cudaGetSymbolAddress((void**)&a, g_a);
    cudaGetSymbolAddress((void**)&pv, g_pv);
    cudaGetSymbolAddress((void**)&agg, g_agg);
    cudaGetSymbolAddress((void**)&pos, g_pos);
    cudaGetSymbolAddress((void**)&ew, g_ew);
    cudaGetSymbolAddress((void**)&ews, g_ews);
    cudaGetSymbolAddress((void**)&parsing, g_parsing);
    cudaGetSymbolAddress((void**)&ms, g_ms);
    cudaGetSymbolAddress((void**)&cnt, g_cnt);
    cudaGetSymbolAddress((void**)&off, g_off);
    cudaGetSymbolAddress((void**)&cur, g_cur);
    cudaGetSymbolAddress((void**)&csrc, g_csrc);
    cudaGetSymbolAddress((void**)&ceid, g_ceid);
    cudaGetSymbolAddress((void**)&sum2, g_sum2);

    const int GM = (NN + 127) / 128;  // 782

    // dtype detection + zeroing
    detect_kernel<<<1, 1024>>>((const unsigned long long*)ei);
    cudaMemsetAsync(cnt, 0, NN * sizeof(int));
    cudaMemsetAsync(sum2, 0, 2 * sizeof(double));

    // parsing = relu(2*P0)
    parsing_kernel<<<16, 256>>>(P0);

    // pseudo-MLP chain: h1 = relu(x@Wm1+bm1); h2 = relu(h1@Wm2+bm2); logits = h2@Wm3+bm3
    sgemm_f2<128, 128, 16, EPI_BIAS | EPI_RELU><<<dim3(GM, 4), 256>>>(x, Wm1, bm1, nullptr, h1, NN, 128, 512);
    sgemm_f2<128, 64, 16, EPI_BIAS | EPI_RELU><<<dim3(GM, 1), 128>>>(h1, Wm2, bm2, nullptr, h2, NN, 512, 64);
    sgemm_f2<128, 64, 16, EPI_BIAS><<<dim3(GM, 1), 128>>>(h2, Wm3, bm3, nullptr, logits, NN, 64, 64);
    sgemm_f2<128, 64, 16, 0><<<dim3(GM, 1), 128>>>(logits, parsing, nullptr, nullptr, tp, NN, 64, 64);

    // initial MLP: xh = relu(x@Wi1+bi1)@Wi2+bi2
    sgemm_f2<128, 128, 16, EPI_BIAS | EPI_RELU><<<dim3(GM, 1), 256>>>(x, Wi1, bi1, nullptr, tmp, NN, 128, 128);
    sgemm_f2<128, 128, 16, EPI_BIAS><<<dim3(GM, 1), 256>>>(tmp, Wi2, bi2, nullptr, xh, NN, 128, 128);

    // pos = relu(xh@Wp1+bp1)@Wp2+bp2 ; pv = pos@WlB
    sgemm_f2<128, 128, 16, EPI_BIAS | EPI_RELU><<<dim3(GM, 1), 256>>>(xh, Wp1, bp1, nullptr, tmp, NN, 128, 128);
    pos_kernel<<<12500, 256>>>(tmp, Wp2, bp2, pos);
    pv_kernel<<<50000, 256>>>(pos, Wl + 128 * 128, pv);

    // CSR build by dst
    count_kernel<<<6250, 256>>>(ei, cnt);
    scan_kernel<<<1, 1024>>>(cnt, off, cur);
    scatter_kernel<<<6250, 256>>>(ei, cur, csrc, ceid);

    // edge weights + normalization (fused into CSR-order permute)
    ew_kernel<<<200000, 256>>>(ei, logits, tp, ew, sum2);
    finalize_kernel<<<1, 1>>>(sum2, ms);
    ewperm_kernel<<<6250, 256>>>(ew, ceid, ms, ews);

    // 2 PointNetConv layers (shared weights)
    for (int layer = 0; layer < 2; layer++) {
        // a = xh@WlA + bl + pv
        sgemm_f2<128, 128, 16, EPI_BIAS | EPI_ADDC><<<dim3(GM, 1), 256>>>(xh, Wl, bl, pv, a, NN, 128, 128);
        // agg = segment_max over dst of (a[src]-pv[dst])*ew
        agg_kernel<<<12500, 256>>>(off, csrc, ews, a, pv, agg);
        // xh = relu(agg@Wg + bg)
        sgemm_f2<128, 128, 16, EPI_BIAS | EPI_RELU><<<dim3(GM, 1), 256>>>(agg, Wg, bg, nullptr, xh, NN, 128, 128);
    }

    // out = xh@Wf + bf
    sgemm_f2<128, 64, 16, EPI_BIAS><<<dim3(GM, 1), 128>>>(xh, Wf, bf, nullptr, out, NN, 128, 64);
}

// round 10
// speedup vs baseline: 1.4370x; 1.4370x over previous
#include <cuda_runtime.h>
#include <math.h>
#include <stdint.h>

typedef unsigned long long ull;

static const int NN = 100000;
static const int EE = 1600000;

#define EPI_RELU 1
#define EPI_BIAS 2
#define EPI_ADDC 4

// ============================================================================
// cp.async helpers (sm_80+, valid on compute_103)
// ============================================================================
#define CP_ASYNC16(dst_u32, src_ptr) \
    asm volatile("cp.async.cg.shared.global [%0], [%1], 16;" \
                 :: "r"(dst_u32), "l"(src_ptr) : "memory")
#define CP_COMMIT() asm volatile("cp.async.commit_group;" ::: "memory")
#define CP_WAIT0() asm volatile("cp.async.wait_group 0;" ::: "memory")
#define CP_WAIT1() asm volatile("cp.async.wait_group 1;" ::: "memory")

__device__ __forceinline__ uint32_t smem_u32(const void* p) {
    uint32_t a;
    asm("{ .reg .u64 t; cvta.to.shared.u64 t, %1; cvt.u32.u64 %0, t; }"
        : "=r"(a) : "l"(p));
    return a;
}

// bf16 m16n8k16 MMA, fp32 accumulate
#define MMA_BF16(c, a, b) \
    asm volatile( \
        "mma.sync.aligned.m16n8k16.row.col.f32.bf16.bf16.f32 " \
        "{%0,%1,%2,%3}, {%4,%5,%6,%7}, {%8,%9}, {%0,%1,%2,%3};" \
        : "+f"((c)[0]), "+f"((c)[1]), "+f"((c)[2]), "+f"((c)[3]) \
        : "r"((a)[0]), "r"((a)[1]), "r"((a)[2]), "r"((a)[3]), \
          "r"((b)[0]), "r"((b)[1]))

// Split a float2 into packed bf16x2 hi (rounded) and lo (residual, bf16).
// hi.lo_half = bf16(v.x), hi.hi_half = bf16(v.y); lo likewise of residuals.
__device__ __forceinline__ void split_bf16(float2 v, uint32_t& hi, uint32_t& lo) {
    uint32_t h;
    asm("cvt.rn.bf16x2.f32 %0, %1, %2;" : "=r"(h) : "f"(v.y), "f"(v.x));
    float hx = __uint_as_float(h << 16);
    float hy = __uint_as_float(h & 0xffff0000u);
    float rx = v.x - hx;
    float ry = v.y - hy;
    uint32_t l;
    asm("cvt.rn.bf16x2.f32 %0, %1, %2;" : "=r"(l) : "f"(ry), "f"(rx));
    hi = h;
    lo = l;
}

// ============================================================================
// Scratch (device globals; no allocation allowed)
// ============================================================================
__device__ float g_h1[100000 * 512];
__device__ float g_h2[100000 * 64];
__device__ float g_logits[100000 * 64];
__device__ float g_tp[100000 * 64];
__device__ float g_xh[100000 * 128];
__device__ float g_tmp[100000 * 128];
__device__ float g_a[100000 * 128];
__device__ float g_pv[100000 * 128];
__device__ float g_agg[100000 * 128];
__device__ float g_pos[100000 * 3];
__device__ float g_ew[1600000];
__device__ float g_ews[1600000];
__device__ int   g_cnt[100000];
__device__ int   g_off[100001];
__device__ int   g_cur[100000];
__device__ int   g_csrc[1600000];
__device__ int   g_ceid[1600000];
__device__ double g_sum2[2];
__device__ float g_ms[2];
__device__ int   g_is64;
// transposed weights [N,K]
__device__ float g_btm1[512 * 128];
__device__ float g_btm2[64 * 512];
__device__ float g_btm3[64 * 64];
__device__ float g_pt[64 * 64];
__device__ float g_bti1[128 * 128];
__device__ float g_bti2[128 * 128];
__device__ float g_btp1[128 * 128];
__device__ float g_btlA[128 * 128];
__device__ float g_btg[128 * 128];
__device__ float g_btf[64 * 128];

// ----------------------------------------------------------------------------
// Edge index loader (handles int64 or int32 edge_index)
// ----------------------------------------------------------------------------
__device__ __forceinline__ int load_edge(const void* ei, int which, int e) {
    if (g_is64)
        return (int)reinterpret_cast<const long long*>(ei)[(size_t)which * EE + e];
    return reinterpret_cast<const int*>(ei)[(size_t)which * EE + e];
}

__global__ void detect_kernel(const unsigned long long* p) {
    __shared__ int bad;
    if (threadIdx.x == 0) bad = 0;
    __syncthreads();
    if (p[threadIdx.x] >= 100000ULL) atomicAdd(&bad, 1);
    __syncthreads();
    if (threadIdx.x == 0) g_is64 = (bad == 0) ? 1 : 0;
}

// ----------------------------------------------------------------------------
// Weight transpose: Bt[n*K+k] = W[k*N+n]
// ----------------------------------------------------------------------------
__global__ void transpose_kernel(const float* __restrict__ W, float* __restrict__ Bt,
                                 int K, int N) {
    int i = blockIdx.x * blockDim.x + threadIdx.x;
    if (i >= K * N) return;
    int k = i / N, n = i % N;
    Bt[(size_t)n * K + k] = W[i];
}

// parsingT[n*64+k] = relu(2 * P0[k*64+n])
__global__ void parsingT_kernel(const float* __restrict__ P0, float* __restrict__ PT) {
    int i = blockIdx.x * blockDim.x + threadIdx.x;
    if (i >= 64 * 64) return;
    int k = i / 64, n = i % 64;
    PT[n * 64 + k] = fmaxf(0.f, 2.0f * P0[i]);
}

// ============================================================================
// bf16x3 (fp32-emulating) mma.sync GEMM:
// C[:, colBase..colBase+NT) = epi(A[M,K] @ Bt^T)
// Bt is [Ntot,K] row-major. Tile 128xNT, BK=32, 8 warps (2Mx4N), warp 64x(NT/4).
// Each fp32 operand split hi/lo bf16; D += ah*bh + ah*bl + al*bh.
// Double-buffered fp32 smem staging via cp.async.
// ============================================================================
template <int NT, int EPI>
__global__ void __launch_bounds__(256, 2)
mma_gemm(const float* __restrict__ A, const float* __restrict__ Bt,
         const float* __restrict__ bias, const float* __restrict__ Cadd,
         float* __restrict__ C, int M, int K, int Nld) {
    constexpr int BM = 128, LDK = 40;
    constexpr int WN = NT / 4;       // warp N extent (4 warps in N)
    constexpr int MM = 4;            // 4 mma tiles in M (64 rows per warp)
    constexpr int MN = WN / 8;       // mma tiles in N
    extern __shared__ float sm[];
    float* As = sm;                    // [2][BM][LDK]
    float* Bs = sm + 2 * BM * LDK;     // [2][NT][LDK]
    const uint32_t as_b = smem_u32(As);
    const uint32_t bs_b = smem_u32(Bs);

    const int tid = threadIdx.x;
    const int lane = tid & 31;
    const int wid = tid >> 5;
    const int warp_m = wid & 1;
    const int warp_n = wid >> 1;
    const int g = lane >> 2;
    const int tig = lane & 3;

    const int rowBase = blockIdx.x * BM;
    const int colBase = blockIdx.y * NT;
    const float* Bt2 = Bt + (size_t)colBase * K;

    float acc[MM][MN][4];
#pragma unroll
    for (int i = 0; i < MM; i++)
#pragma unroll
        for (int j = 0; j < MN; j++)
#pragma unroll
            for (int q = 0; q < 4; q++) acc[i][j][q] = 0.f;

    const int nCh = K >> 5;

    auto load_stage = [&](int buf, int k0) {
#pragma unroll
        for (int i = 0; i < 4; i++) {
            int q = tid + i * 256;           // 1024 chunks for A
            int r = q >> 3, cc = q & 7;
            int gr = rowBase + r;
            if (gr >= M) gr = M - 1;
            const float* src = A + (size_t)gr * K + k0 + cc * 4;
            uint32_t dst = as_b + (uint32_t)((buf * BM * LDK + r * LDK + cc * 4) * 4);
            CP_ASYNC16(dst, src);
        }
#pragma unroll
        for (int i = 0; i < NT / 32; i++) {
            int q = tid + i * 256;           // NT*8 chunks for B
            int r = q >> 3, cc = q & 7;
            const float* src = Bt2 + (size_t)r * K + k0 + cc * 4;
            uint32_t dst = bs_b + (uint32_t)((buf * NT * LDK + r * LDK + cc * 4) * 4);
            CP_ASYNC16(dst, src);
        }
        CP_COMMIT();
    };

    load_stage(0, 0);
    if (nCh > 1) load_stage(1, 32);

    for (int c = 0; c < nCh; c++) {
        if (c == nCh - 1) { CP_WAIT0(); } else { CP_WAIT1(); }
        __syncthreads();
        const int buf = c & 1;
        const float* Ab = As + buf * BM * LDK;
        const float* Bb = Bs + buf * NT * LDK;
#pragma unroll
        for (int ko = 0; ko < 2; ko++) {
            const int k16 = ko * 16;
            // B fragments (hi/lo) for all MN tiles
            uint32_t bhi[MN][2], blo[MN][2];
#pragma unroll
            for (int mn = 0; mn < MN; mn++) {
                const float* p = Bb + (warp_n * WN + mn * 8 + g) * LDK + k16 + 2 * tig;
                float2 v0 = *reinterpret_cast<const float2*>(p);
                float2 v1 = *reinterpret_cast<const float2*>(p + 8);
                split_bf16(v0, bhi[mn][0], blo[mn][0]);
                split_bf16(v1, bhi[mn][1], blo[mn][1]);
            }
#pragma unroll
            for (int mm = 0; mm < MM; mm++) {
                const float* p = Ab + (warp_m * 64 + mm * 16 + g) * LDK + k16 + 2 * tig;
                float2 u0 = *reinterpret_cast<const float2*>(p);
                float2 u1 = *reinterpret_cast<const float2*>(p + 8 * LDK);
                float2 u2 = *reinterpret_cast<const float2*>(p + 8);
                float2 u3 = *reinterpret_cast<const float2*>(p + 8 * LDK + 8);
                uint32_t ahi[4], alo[4];
                split_bf16(u0, ahi[0], alo[0]);
                split_bf16(u1, ahi[1], alo[1]);
                split_bf16(u2, ahi[2], alo[2]);
                split_bf16(u3, ahi[3], alo[3]);
#pragma unroll
                for (int mn = 0; mn < MN; mn++) {
                    MMA_BF16(acc[mm][mn], ahi, bhi[mn]);
                    MMA_BF16(acc[mm][mn], ahi, blo[mn]);
                    MMA_BF16(acc[mm][mn], alo, bhi[mn]);
                }
            }
        }
        __syncthreads();
        if (c + 2 < nCh) load_stage(buf, (c + 2) * 32);
    }

    // Epilogue
#pragma unroll
    for (int mm = 0; mm < MM; mm++) {
        const int r0 = rowBase + warp_m * 64 + mm * 16 + g;
        const int r1 = r0 + 8;
#pragma unroll
        for (int mn = 0; mn < MN; mn++) {
            const int col = colBase + warp_n * WN + mn * 8 + 2 * tig;
            float2 v0 = make_float2(acc[mm][mn][0], acc[mm][mn][1]);
            float2 v1 = make_float2(acc[mm][mn][2], acc[mm][mn][3]);
            if (EPI & EPI_BIAS) {
                float2 bb = *reinterpret_cast<const float2*>(bias + col);
                v0.x += bb.x; v0.y += bb.y;
                v1.x += bb.x; v1.y += bb.y;
            }
            if (r0 < M) {
                float2 o = v0;
                if (EPI & EPI_ADDC) {
                    float2 cc = *reinterpret_cast<const float2*>(Cadd + (size_t)r0 * Nld + col);
                    o.x += cc.x; o.y += cc.y;
                }
                if (EPI & EPI_RELU) { o.x = fmaxf(o.x, 0.f); o.y = fmaxf(o.y, 0.f); }
                *reinterpret_cast<float2*>(C + (size_t)r0 * Nld + col) = o;
            }
            if (r1 < M) {
                float2 o = v1;
                if (EPI & EPI_ADDC) {
                    float2 cc = *reinterpret_cast<const float2*>(Cadd + (size_t)r1 * Nld + col);
                    o.x += cc.x; o.y += cc.y;
                }
                if (EPI & EPI_RELU) { o.x = fmaxf(o.x, 0.f); o.y = fmaxf(o.y, 0.f); }
                *reinterpret_cast<float2*>(C + (size_t)r1 * Nld + col) = o;
            }
        }
    }
}

// ----------------------------------------------------------------------------
// ew[e] = dot64(logits[src], tp[dst]); accumulate sum & sumsq (double)
// ----------------------------------------------------------------------------
__global__ void ew_kernel(const void* __restrict__ ei, const float* __restrict__ logits,
                          const float* __restrict__ tp, float* __restrict__ ew,
                          double* __restrict__ sum2) {
    int gw = (blockIdx.x * blockDim.x + threadIdx.x) >> 5;
    int lane = threadIdx.x & 31;
    int wib = threadIdx.x >> 5;
    __shared__ float sv[8], sq[8];
    float val = 0.f;
    bool valid = gw < EE;
    if (valid) {
        int s = load_edge(ei, 0, gw);
        int d = load_edge(ei, 1, gw);
        float2 la = reinterpret_cast<const float2*>(logits + (size_t)s * 64)[lane];
        float2 tb = reinterpret_cast<const float2*>(tp + (size_t)d * 64)[lane];
        val = la.x * tb.x + la.y * tb.y;
#pragma unroll
        for (int o = 16; o; o >>= 1) val += __shfl_down_sync(0xffffffffu, val, o);
        if (lane == 0) ew[gw] = val;
    }
    if (lane == 0) {
        sv[wib] = valid ? val : 0.f;
        sq[wib] = valid ? val * val : 0.f;
    }
    __syncthreads();
    if (threadIdx.x == 0) {
        double s = 0, q = 0;
#pragma unroll
        for (int i = 0; i < 8; i++) { s += (double)sv[i]; q += (double)sq[i]; }
        atomicAdd(sum2 + 0, s);
        atomicAdd(sum2 + 1, q);
    }
}

__global__ void finalize_kernel(const double* __restrict__ sum2, float* __restrict__ ms) {
    double s = sum2[0], q = sum2[1];
    double Ed = (double)EE;
    double mean = s / Ed;
    double var = (q - s * s / Ed) / (Ed - 1.0);
    ms[0] = (float)mean;
    ms[1] = (float)sqrt(1e-4 / var);
}

// ----------------------------------------------------------------------------
// CSR build
// ----------------------------------------------------------------------------
__global__ void count_kernel(const void* __restrict__ ei, int* __restrict__ cnt) {
    int e = blockIdx.x * blockDim.x + threadIdx.x;
    if (e >= EE) return;
    atomicAdd(&cnt[load_edge(ei, 1, e)], 1);
}

__global__ void scan_kernel(const int* __restrict__ cnt, int* __restrict__ off,
                            int* __restrict__ cur) {
    __shared__ int sh[1024];
    const int T = 1024;
    int tid = threadIdx.x;
    const int CH = (NN + T - 1) / T;
    int b0 = tid * CH;
    int loc = 0;
    for (int i = 0; i < CH; i++) {
        int idx = b0 + i;
        if (idx < NN) loc += cnt[idx];
    }
    sh[tid] = loc;
    __syncthreads();
    for (int o = 1; o < T; o <<= 1) {
        int t = (tid >= o) ? sh[tid - o] : 0;
        __syncthreads();
        sh[tid] += t;
        __syncthreads();
    }
    int excl = sh[tid] - loc;
    int run = excl;
    for (int i = 0; i < CH; i++) {
        int idx = b0 + i;
        if (idx < NN) {
            off[idx] = run;
            cur[idx] = run;
            run += cnt[idx];
        }
    }
    if (tid == T - 1) off[NN] = EE;
}

__global__ void scatter_kernel(const void* __restrict__ ei, int* __restrict__ cur,
                               int* __restrict__ csrc, int* __restrict__ ceid) {
    int e = blockIdx.x * blockDim.x + threadIdx.x;
    if (e >= EE) return;
    int d = load_edge(ei, 1, e);
    int p = atomicAdd(&cur[d], 1);
    csrc[p] = load_edge(ei, 0, e);
    ceid[p] = e;
}

__global__ void ewperm_kernel(const float* __restrict__ ew, const int* __restrict__ ceid,
                              const float* __restrict__ ms, float* __restrict__ ews) {
    int i = blockIdx.x * blockDim.x + threadIdx.x;
    if (i >= EE) return;
    ews[i] = (__ldg(ew + __ldg(ceid + i)) - ms[0]) * ms[1] + 1.0f;
}

// ----------------------------------------------------------------------------
// pos = t2 @ Wp2 + bp2 (K=128, Nout=3). One warp per node.
// ----------------------------------------------------------------------------
__global__ void pos_kernel(const float* __restrict__ t2, const float* __restrict__ Wp2,
                           const float* __restrict__ bp2, float* __restrict__ pos) {
    __shared__ float sw[384];
    for (int i = threadIdx.x; i < 384; i += blockDim.x) sw[i] = Wp2[i];
    __syncthreads();
    int gw = (blockIdx.x * blockDim.x + threadIdx.x) >> 5;
    int lane = threadIdx.x & 31;
    if (gw >= NN) return;
    float4 v = *reinterpret_cast<const float4*>(t2 + (size_t)gw * 128 + lane * 4);
    int k0 = lane * 4;
    float p0 = v.x * sw[k0 * 3 + 0] + v.y * sw[(k0 + 1) * 3 + 0] +
               v.z * sw[(k0 + 2) * 3 + 0] + v.w * sw[(k0 + 3) * 3 + 0];
    float p1 = v.x * sw[k0 * 3 + 1] + v.y * sw[(k0 + 1) * 3 + 1] +
               v.z * sw[(k0 + 2) * 3 + 1] + v.w * sw[(k0 + 3) * 3 + 1];
    float p2 = v.x * sw[k0 * 3 + 2] + v.y * sw[(k0 + 1) * 3 + 2] +
               v.z * sw[(k0 + 2) * 3 + 2] + v.w * sw[(k0 + 3) * 3 + 2];
#pragma unroll
    for (int o = 16; o; o >>= 1) {
        p0 += __shfl_down_sync(0xffffffffu, p0, o);
        p1 += __shfl_down_sync(0xffffffffu, p1, o);
        p2 += __shfl_down_sync(0xffffffffu, p2, o);
    }
    if (lane == 0) {
        pos[gw * 3 + 0] = p0 + __ldg(bp2 + 0);
        pos[gw * 3 + 1] = p1 + __ldg(bp2 + 1);
        pos[gw * 3 + 2] = p2 + __ldg(bp2 + 2);
    }
}

__global__ void pv_kernel(const float* __restrict__ pos, const float* __restrict__ WlB,
                          float* __restrict__ pv) {
    int idx = blockIdx.x * blockDim.x + threadIdx.x;
    if (idx >= NN * 128) return;
    int n = idx >> 7, j = idx & 127;
    float p0 = __ldg(pos + n * 3 + 0);
    float p1 = __ldg(pos + n * 3 + 1);
    float p2 = __ldg(pos + n * 3 + 2);
    pv[idx] = p0 * __ldg(WlB + j) + p1 * __ldg(WlB + 128 + j) + p2 * __ldg(WlB + 256 + j);
}

// ----------------------------------------------------------------------------
// Aggregation: warp per dst node; agg[n] = max_e ((a[src]-pv[n]) * ew_s[e]); empty -> 0
// ----------------------------------------------------------------------------
__global__ void agg_kernel(const int* __restrict__ off, const int* __restrict__ csrc,
                           const float* __restrict__ ews, const float* __restrict__ a,
                           const float* __restrict__ pv, float* __restrict__ agg) {
    int gw = (blockIdx.x * blockDim.x + threadIdx.x) >> 5;
    int lane = threadIdx.x & 31;
    if (gw >= NN) return;
    int beg = __ldg(off + gw), end = __ldg(off + gw + 1);
    float4 pvd = *reinterpret_cast<const float4*>(pv + (size_t)gw * 128 + lane * 4);
    float mx0 = -INFINITY, mx1 = -INFINITY, mx2 = -INFINITY, mx3 = -INFINITY;
    int e = beg;
    int sN = 0;
    float wN = 0.f;
    if (e < end) { sN = __ldg(csrc + e); wN = __ldg(ews + e); }
    for (; e < end; e++) {
        int s = sN;
        float w = wN;
        if (e + 1 < end) { sN = __ldg(csrc + e + 1); wN = __ldg(ews + e + 1); }
        float4 av = *reinterpret_cast<const float4*>(a + (size_t)s * 128 + lane * 4);
        mx0 = fmaxf(mx0, (av.x - pvd.x) * w);
        mx1 = fmaxf(mx1, (av.y - pvd.y) * w);
        mx2 = fmaxf(mx2, (av.z - pvd.z) * w);
        mx3 = fmaxf(mx3, (av.w - pvd.w) * w);
    }
    float4 r = (beg == end) ? make_float4(0.f, 0.f, 0.f, 0.f)
                            : make_float4(mx0, mx1, mx2, mx3);
    *reinterpret_cast<float4*>(agg + (size_t)gw * 128 + lane * 4) = r;
}

// ----------------------------------------------------------------------------
// Host launcher
// ----------------------------------------------------------------------------
extern "C" void kernel_launch(void* const* d_in, const int* in_sizes, int n_in,
                              void* d_out, int out_size) {
    const float* x   = (const float*)d_in[0];
    const void*  ei  = d_in[1];
    const float* Wm1 = (const float*)d_in[2];  const float* bm1 = (const float*)d_in[3];
    const float* Wm2 = (const float*)d_in[4];  const float* bm2 = (const float*)d_in[5];
    const float* Wm3 = (const float*)d_in[6];  const float* bm3 = (const float*)d_in[7];
    const float* P0  = (const float*)d_in[8];
    const float* Wi1 = (const float*)d_in[9];  const float* bi1 = (const float*)d_in[10];
    const float* Wi2 = (const float*)d_in[11]; const float* bi2 = (const float*)d_in[12];
    const float* Wp1 = (const float*)d_in[13]; const float* bp1 = (const float*)d_in[14];
    const float* Wp2 = (const float*)d_in[15]; const float* bp2 = (const float*)d_in[16];
    const float* Wl  = (const float*)d_in[17]; const float* bl  = (const float*)d_in[18];
    const float* Wg  = (const float*)d_in[19]; const float* bg  = (const float*)d_in[20];
    const float* Wf  = (const float*)d_in[21]; const float* bf  = (const float*)d_in[22];
    float* out = (float*)d_out;

    float *h1, *h2, *logits, *tp, *xh, *tmp, *a, *pv, *agg, *pos, *ew, *ews, *ms;
    float *btm1, *btm2, *btm3, *pt, *bti1, *bti2, *btp1, *btlA, *btg, *btf;
    int *cnt, *off, *cur, *csrc, *ceid;
    double* sum2;
    cudaGetSymbolAddress((void**)&h1, g_h1);
    cudaGetSymbolAddress((void**)&h2, g_h2);
    cudaGetSymbolAddress((void**)&logits, g_logits);
    cudaGetSymbolAddress((void**)&tp, g_tp);
    cudaGetSymbolAddress((void**)&xh, g_xh);
    cudaGetSymbolAddress((void**)&tmp, g_tmp);
    cudaGetSymbolAddress((void**)&a, g_a);
    cudaGetSymbolAddress((void**)&pv, g_pv);
    cudaGetSymbolAddress((void**)&agg, g_agg);
    cudaGetSymbolAddress((void**)&pos, g_pos);
    cudaGetSymbolAddress((void**)&ew, g_ew);
    cudaGetSymbolAddress((void**)&ews, g_ews);
    cudaGetSymbolAddress((void**)&ms, g_ms);
    cudaGetSymbolAddress((void**)&cnt, g_cnt);
    cudaGetSymbolAddress((void**)&off, g_off);
    cudaGetSymbolAddress((void**)&cur, g_cur);
    cudaGetSymbolAddress((void**)&csrc, g_csrc);
    cudaGetSymbolAddress((void**)&ceid, g_ceid);
    cudaGetSymbolAddress((void**)&sum2, g_sum2);
    cudaGetSymbolAddress((void**)&btm1, g_btm1);
    cudaGetSymbolAddress((void**)&btm2, g_btm2);
    cudaGetSymbolAddress((void**)&btm3, g_btm3);
    cudaGetSymbolAddress((void**)&pt, g_pt);
    cudaGetSymbolAddress((void**)&bti1, g_bti1);
    cudaGetSymbolAddress((void**)&bti2, g_bti2);
    cudaGetSymbolAddress((void**)&btp1, g_btp1);
    cudaGetSymbolAddress((void**)&btlA, g_btlA);
    cudaGetSymbolAddress((void**)&btg, g_btg);
    cudaGetSymbolAddress((void**)&btf, g_btf);

    const int GM = (NN + 127) / 128;  // 782
    const int SM128 = 2 * 40 * (128 + 128) * 4;  // 81920
    const int SM64  = 2 * 40 * (128 + 64) * 4;   // 61440

    cudaFuncSetAttribute(mma_gemm<128, EPI_BIAS | EPI_RELU>,
                         cudaFuncAttributeMaxDynamicSharedMemorySize, SM128);
    cudaFuncSetAttribute(mma_gemm<128, EPI_BIAS>,
                         cudaFuncAttributeMaxDynamicSharedMemorySize, SM128);
    cudaFuncSetAttribute(mma_gemm<128, EPI_BIAS | EPI_ADDC>,
                         cudaFuncAttributeMaxDynamicSharedMemorySize, SM128);
    cudaFuncSetAttribute(mma_gemm<64, EPI_BIAS | EPI_RELU>,
                         cudaFuncAttributeMaxDynamicSharedMemorySize, SM64);
    cudaFuncSetAttribute(mma_gemm<64, EPI_BIAS>,
                         cudaFuncAttributeMaxDynamicSharedMemorySize, SM64);
    cudaFuncSetAttribute(mma_gemm<64, 0>,
                         cudaFuncAttributeMaxDynamicSharedMemorySize, SM64);

    // dtype detection + zeroing
    detect_kernel<<<1, 1024>>>((const unsigned long long*)ei);
    cudaMemsetAsync(cnt, 0, NN * sizeof(int));
    cudaMemsetAsync(sum2, 0, 2 * sizeof(double));

    // Weight transposes ([K,N] -> [N,K]) + parsing
#define TR(W, BT, K, N) transpose_kernel<<<((K) * (N) + 255) / 256, 256>>>(W, BT, K, N)
    TR(Wm1, btm1, 128, 512);
    TR(Wm2, btm2, 512, 64);
    TR(Wm3, btm3, 64, 64);
    TR(Wi1, bti1, 128, 128);
    TR(Wi2, bti2, 128, 128);
    TR(Wp1, btp1, 128, 128);
    TR(Wl,  btlA, 128, 128);   // first 128 rows of Wl
    TR(Wg,  btg,  128, 128);
    TR(Wf,  btf,  128, 64);
#undef TR
    parsingT_kernel<<<16, 256>>>(P0, pt);

    // CSR build (independent of GEMMs)
    count_kernel<<<6250, 256>>>(ei, cnt);
    scan_kernel<<<1, 1024>>>(cnt, off, cur);
    scatter_kernel<<<6250, 256>>>(ei, cur, csrc, ceid);

    // pseudo-MLP chain
    mma_gemm<128, EPI_BIAS | EPI_RELU><<<dim3(GM, 4), 256, SM128>>>(x, btm1, bm1, nullptr, h1, NN, 128, 512);
    mma_gemm<64, EPI_BIAS | EPI_RELU><<<dim3(GM, 1), 256, SM64>>>(h1, btm2, bm2, nullptr, h2, NN, 512, 64);
    mma_gemm<64, EPI_BIAS><<<dim3(GM, 1), 256, SM64>>>(h2, btm3, bm3, nullptr, logits, NN, 64, 64);
    mma_gemm<64, 0><<<dim3(GM, 1), 256, SM64>>>(logits, pt, nullptr, nullptr, tp, NN, 64, 64);

    // initial MLP
    mma_gemm<128, EPI_BIAS | EPI_RELU><<<dim3(GM, 1), 256, SM128>>>(x, bti1, bi1, nullptr, tmp, NN, 128, 128);
    mma_gemm<128, EPI_BIAS><<<dim3(GM, 1), 256, SM128>>>(tmp, bti2, bi2, nullptr, xh, NN, 128, 128);

    // pos / pv
    mma_gemm<128, EPI_BIAS | EPI_RELU><<<dim3(GM, 1), 256, SM128>>>(xh, btp1, bp1, nullptr, tmp, NN, 128, 128);
    pos_kernel<<<12500, 256>>>(tmp, Wp2, bp2, pos);
    pv_kernel<<<50000, 256>>>(pos, Wl + 128 * 128, pv);

    // edge weights + normalization
    ew_kernel<<<200000, 256>>>(ei, logits, tp, ew, sum2);
    finalize_kernel<<<1, 1>>>(sum2, ms);
    ewperm_kernel<<<6250, 256>>>(ew, ceid, ms, ews);

    // 2 PointNetConv layers (shared weights)
    for (int layer = 0; layer < 2; layer++) {
        mma_gemm<128, EPI_BIAS | EPI_ADDC><<<dim3(GM, 1), 256, SM128>>>(xh, btlA, bl, pv, a, NN, 128, 128);
        agg_kernel<<<12500, 256>>>(off, csrc, ews, a, pv, agg);
        mma_gemm<128, EPI_BIAS | EPI_RELU><<<dim3(GM, 1), 256, SM128>>>(agg, btg, bg, nullptr, xh, NN, 128, 128);
    }

    // out = xh @ Wf + bf
    mma_gemm<64, EPI_BIAS><<<dim3(GM, 1), 256, SM64>>>(xh, btf, bf, nullptr, out, NN, 128, 64);
}

// round 11
// speedup vs baseline: 2.0340x; 1.4155x over previous
#include <cuda_runtime.h>
#include <math.h>
#include <stdint.h>

typedef unsigned long long ull;

static const int NN = 100000;
static const int EE = 1600000;

#define EPI_RELU 1
#define EPI_BIAS 2
#define EPI_ADDC 4

// ============================================================================
// cp.async helpers (sm_80+, valid on compute_103)
// ============================================================================
#define CP_ASYNC16(dst_u32, src_ptr) \
    asm volatile("cp.async.cg.shared.global [%0], [%1], 16;" \
                 :: "r"(dst_u32), "l"(src_ptr) : "memory")
#define CP_COMMIT() asm volatile("cp.async.commit_group;" ::: "memory")
#define CP_WAIT0() asm volatile("cp.async.wait_group 0;" ::: "memory")
#define CP_WAIT1() asm volatile("cp.async.wait_group 1;" ::: "memory")

__device__ __forceinline__ uint32_t smem_u32(const void* p) {
    uint32_t a;
    asm("{ .reg .u64 t; cvta.to.shared.u64 t, %1; cvt.u32.u64 %0, t; }"
        : "=r"(a) : "l"(p));
    return a;
}

// bf16 m16n8k16 MMA, fp32 accumulate
#define MMA_BF16(c, a, b) \
    asm volatile( \
        "mma.sync.aligned.m16n8k16.row.col.f32.bf16.bf16.f32 " \
        "{%0,%1,%2,%3}, {%4,%5,%6,%7}, {%8,%9}, {%0,%1,%2,%3};" \
        : "+f"((c)[0]), "+f"((c)[1]), "+f"((c)[2]), "+f"((c)[3]) \
        : "r"((a)[0]), "r"((a)[1]), "r"((a)[2]), "r"((a)[3]), \
          "r"((b)[0]), "r"((b)[1]))

// Split a float2 into packed bf16x2 hi (rounded) and lo (residual, bf16).
__device__ __forceinline__ void split_bf16(float2 v, uint32_t& hi, uint32_t& lo) {
    uint32_t h;
    asm("cvt.rn.bf16x2.f32 %0, %1, %2;" : "=r"(h) : "f"(v.y), "f"(v.x));
    float hx = __uint_as_float(h << 16);
    float hy = __uint_as_float(h & 0xffff0000u);
    float rx = v.x - hx;
    float ry = v.y - hy;
    uint32_t l;
    asm("cvt.rn.bf16x2.f32 %0, %1, %2;" : "=r"(l) : "f"(ry), "f"(rx));
    hi = h;
    lo = l;
}

// ============================================================================
// Scratch (device globals; no allocation allowed)
// ============================================================================
__device__ float g_h1[100000 * 512];
__device__ float g_h2[100000 * 64];
__device__ float g_logits[100000 * 64];
__device__ float g_tp[100000 * 64];
__device__ float g_xh[100000 * 128];
__device__ float g_tmp[100000 * 128];
__device__ float g_a[100000 * 128];
__device__ float g_pv[100000 * 128];
__device__ float g_agg[100000 * 128];
__device__ float g_pos[100000 * 3];
__device__ float g_ew[1600000];
__device__ float g_cew[1600000];
__device__ int   g_cnt[100000];
__device__ int   g_off[100001];
__device__ int   g_cur[100000];
__device__ int   g_csrc[1600000];
__device__ double g_sum2[2];
__device__ float g_ms[2];
__device__ int   g_is64;
// transposed weights [N,K]
__device__ float g_btm1[512 * 128];
__device__ float g_btm2[64 * 512];
__device__ float g_btm3[64 * 64];
__device__ float g_pt[64 * 64];
__device__ float g_bti1[128 * 128];
__device__ float g_bti2[128 * 128];
__device__ float g_btp1[128 * 128];
__device__ float g_btlA[128 * 128];
__device__ float g_btg[128 * 128];
__device__ float g_btf[64 * 128];

// ----------------------------------------------------------------------------
// Edge index loader (handles int64 or int32 edge_index)
// ----------------------------------------------------------------------------
__device__ __forceinline__ int load_edge(const void* ei, int which, int e) {
    if (g_is64)
        return (int)reinterpret_cast<const long long*>(ei)[(size_t)which * EE + e];
    return reinterpret_cast<const int*>(ei)[(size_t)which * EE + e];
}

// ----------------------------------------------------------------------------
// Fused prep: all weight transposes + parsing + edge-dtype detect.
// 769 blocks x 256 threads. Blocks 0..767 transpose; block 768 detects.
// ----------------------------------------------------------------------------
__global__ void prep_kernel(const ull* __restrict__ ei64,
                            const float* __restrict__ Wm1, const float* __restrict__ Wm2,
                            const float* __restrict__ Wm3, const float* __restrict__ P0,
                            const float* __restrict__ Wi1, const float* __restrict__ Wi2,
                            const float* __restrict__ Wp1, const float* __restrict__ Wl,
                            const float* __restrict__ Wg,  const float* __restrict__ Wf) {
    int base = blockIdx.x * 256;
    if (base >= 196608) {
        __shared__ int bad;
        if (threadIdx.x == 0) bad = 0;
        __syncthreads();
        for (int i = threadIdx.x; i < 1024; i += 256)
            if (ei64[i] >= 100000ULL) atomicAdd(&bad, 1);
        __syncthreads();
        if (threadIdx.x == 0) g_is64 = (bad == 0) ? 1 : 0;
        return;
    }
    int i = base + threadIdx.x;
    if (i < 65536) {                     // Wm1 [128,512]
        int k = i >> 9, n = i & 511;
        g_btm1[n * 128 + k] = Wm1[i];
    } else if (i < 98304) {              // Wm2 [512,64]
        int j = i - 65536; int k = j >> 6, n = j & 63;
        g_btm2[n * 512 + k] = Wm2[j];
    } else if (i < 102400) {             // Wm3 [64,64]
        int j = i - 98304; int k = j >> 6, n = j & 63;
        g_btm3[n * 64 + k] = Wm3[j];
    } else if (i < 106496) {             // parsing [64,64]
        int j = i - 102400; int k = j >> 6, n = j & 63;
        g_pt[n * 64 + k] = fmaxf(0.f, 2.0f * P0[j]);
    } else if (i < 122880) {             // Wi1 [128,128]
        int j = i - 106496; int k = j >> 7, n = j & 127;
        g_bti1[n * 128 + k] = Wi1[j];
    } else if (i < 139264) {             // Wi2
        int j = i - 122880; int k = j >> 7, n = j & 127;
        g_bti2[n * 128 + k] = Wi2[j];
    } else if (i < 155648) {             // Wp1
        int j = i - 139264; int k = j >> 7, n = j & 127;
        g_btp1[n * 128 + k] = Wp1[j];
    } else if (i < 172032) {             // Wl first 128 rows
        int j = i - 155648; int k = j >> 7, n = j & 127;
        g_btlA[n * 128 + k] = Wl[j];
    } else if (i < 188416) {             // Wg
        int j = i - 172032; int k = j >> 7, n = j & 127;
        g_btg[n * 128 + k] = Wg[j];
    } else {                             // Wf [128,64]
        int j = i - 188416; int k = j >> 6, n = j & 63;
        g_btf[n * 128 + k] = Wf[j];
    }
}

// ============================================================================
// bf16x3 (fp32-emulating) mma.sync GEMM (unchanged from round 10 — proven)
// ============================================================================
template <int NT, int EPI>
__global__ void __launch_bounds__(256, 2)
mma_gemm(const float* __restrict__ A, const float* __restrict__ Bt,
         const float* __restrict__ bias, const float* __restrict__ Cadd,
         float* __restrict__ C, int M, int K, int Nld) {
    constexpr int BM = 128, LDK = 40;
    constexpr int WN = NT / 4;
    constexpr int MM = 4;
    constexpr int MN = WN / 8;
    extern __shared__ float sm[];
    float* As = sm;
    float* Bs = sm + 2 * BM * LDK;
    const uint32_t as_b = smem_u32(As);
    const uint32_t bs_b = smem_u32(Bs);

    const int tid = threadIdx.x;
    const int lane = tid & 31;
    const int wid = tid >> 5;
    const int warp_m = wid & 1;
    const int warp_n = wid >> 1;
    const int g = lane >> 2;
    const int tig = lane & 3;

    const int rowBase = blockIdx.x * BM;
    const int colBase = blockIdx.y * NT;
    const float* Bt2 = Bt + (size_t)colBase * K;

    float acc[MM][MN][4];
#pragma unroll
    for (int i = 0; i < MM; i++)
#pragma unroll
        for (int j = 0; j < MN; j++)
#pragma unroll
            for (int q = 0; q < 4; q++) acc[i][j][q] = 0.f;

    const int nCh = K >> 5;

    auto load_stage = [&](int buf, int k0) {
#pragma unroll
        for (int i = 0; i < 4; i++) {
            int q = tid + i * 256;
            int r = q >> 3, cc = q & 7;
            int gr = rowBase + r;
            if (gr >= M) gr = M - 1;
            const float* src = A + (size_t)gr * K + k0 + cc * 4;
            uint32_t dst = as_b + (uint32_t)((buf * BM * LDK + r * LDK + cc * 4) * 4);
            CP_ASYNC16(dst, src);
        }
#pragma unroll
        for (int i = 0; i < NT / 32; i++) {
            int q = tid + i * 256;
            int r = q >> 3, cc = q & 7;
            const float* src = Bt2 + (size_t)r * K + k0 + cc * 4;
            uint32_t dst = bs_b + (uint32_t)((buf * NT * LDK + r * LDK + cc * 4) * 4);
            CP_ASYNC16(dst, src);
        }
        CP_COMMIT();
    };

    load_stage(0, 0);
    if (nCh > 1) load_stage(1, 32);

    for (int c = 0; c < nCh; c++) {
        if (c == nCh - 1) { CP_WAIT0(); } else { CP_WAIT1(); }
        __syncthreads();
        const int buf = c & 1;
        const float* Ab = As + buf * BM * LDK;
        const float* Bb = Bs + buf * NT * LDK;
#pragma unroll
        for (int ko = 0; ko < 2; ko++) {
            const int k16 = ko * 16;
            uint32_t bhi[MN][2], blo[MN][2];
#pragma unroll
            for (int mn = 0; mn < MN; mn++) {
                const float* p = Bb + (warp_n * WN + mn * 8 + g) * LDK + k16 + 2 * tig;
                float2 v0 = *reinterpret_cast<const float2*>(p);
                float2 v1 = *reinterpret_cast<const float2*>(p + 8);
                split_bf16(v0, bhi[mn][0], blo[mn][0]);
                split_bf16(v1, bhi[mn][1], blo[mn][1]);
            }
#pragma unroll
            for (int mm = 0; mm < MM; mm++) {
                const float* p = Ab + (warp_m * 64 + mm * 16 + g) * LDK + k16 + 2 * tig;
                float2 u0 = *reinterpret_cast<const float2*>(p);
                float2 u1 = *reinterpret_cast<const float2*>(p + 8 * LDK);
                float2 u2 = *reinterpret_cast<const float2*>(p + 8);
                float2 u3 = *reinterpret_cast<const float2*>(p + 8 * LDK + 8);
                uint32_t ahi[4], alo[4];
                split_bf16(u0, ahi[0], alo[0]);
                split_bf16(u1, ahi[1], alo[1]);
                split_bf16(u2, ahi[2], alo[2]);
                split_bf16(u3, ahi[3], alo[3]);
#pragma unroll
                for (int mn = 0; mn < MN; mn++) {
                    MMA_BF16(acc[mm][mn], ahi, bhi[mn]);
                    MMA_BF16(acc[mm][mn], ahi, blo[mn]);
                    MMA_BF16(acc[mm][mn], alo, bhi[mn]);
                }
            }
        }
        __syncthreads();
        if (c + 2 < nCh) load_stage(buf, (c + 2) * 32);
    }

#pragma unroll
    for (int mm = 0; mm < MM; mm++) {
        const int r0 = rowBase + warp_m * 64 + mm * 16 + g;
        const int r1 = r0 + 8;
#pragma unroll
        for (int mn = 0; mn < MN; mn++) {
            const int col = colBase + warp_n * WN + mn * 8 + 2 * tig;
            float2 v0 = make_float2(acc[mm][mn][0], acc[mm][mn][1]);
            float2 v1 = make_float2(acc[mm][mn][2], acc[mm][mn][3]);
            if (EPI & EPI_BIAS) {
                float2 bb = *reinterpret_cast<const float2*>(bias + col);
                v0.x += bb.x; v0.y += bb.y;
                v1.x += bb.x; v1.y += bb.y;
            }
            if (r0 < M) {
                float2 o = v0;
                if (EPI & EPI_ADDC) {
                    float2 cc = *reinterpret_cast<const float2*>(Cadd + (size_t)r0 * Nld + col);
                    o.x += cc.x; o.y += cc.y;
                }
                if (EPI & EPI_RELU) { o.x = fmaxf(o.x, 0.f); o.y = fmaxf(o.y, 0.f); }
                *reinterpret_cast<float2*>(C + (size_t)r0 * Nld + col) = o;
            }
            if (r1 < M) {
                float2 o = v1;
                if (EPI & EPI_ADDC) {
                    float2 cc = *reinterpret_cast<const float2*>(Cadd + (size_t)r1 * Nld + col);
                    o.x += cc.x; o.y += cc.y;
                }
                if (EPI & EPI_RELU) { o.x = fmaxf(o.x, 0.f); o.y = fmaxf(o.y, 0.f); }
                *reinterpret_cast<float2*>(C + (size_t)r1 * Nld + col) = o;
            }
        }
    }
}

// ----------------------------------------------------------------------------
// ew[e] = dot64(logits[src], tp[dst]); 8 lanes per edge, xor-reduce.
// Also accumulates sum & sumsq (double) for mean/var.
// ----------------------------------------------------------------------------
__global__ void ew_kernel(const void* __restrict__ ei, const float* __restrict__ logits,
                          const float* __restrict__ tp, float* __restrict__ ew,
                          double* __restrict__ sum2) {
    const int tid = threadIdx.x;
    const int gid = blockIdx.x * 256 + tid;
    const int eg = gid >> 3;
    const int sl = tid & 7;
    const int lane = tid & 31;
    const int wib = tid >> 5;
    const bool valid = eg < EE;
    float val = 0.f;
    if (valid) {
        int s = load_edge(ei, 0, eg);
        int d = load_edge(ei, 1, eg);
        const float4* lp = reinterpret_cast<const float4*>(logits + (size_t)s * 64);
        const float4* tq = reinterpret_cast<const float4*>(tp + (size_t)d * 64);
        float4 a0 = lp[sl * 2], a1 = lp[sl * 2 + 1];
        float4 b0 = tq[sl * 2], b1 = tq[sl * 2 + 1];
        val = a0.x * b0.x + a0.y * b0.y + a0.z * b0.z + a0.w * b0.w +
              a1.x * b1.x + a1.y * b1.y + a1.z * b1.z + a1.w * b1.w;
    }
    val += __shfl_xor_sync(0xffffffffu, val, 4);
    val += __shfl_xor_sync(0xffffffffu, val, 2);
    val += __shfl_xor_sync(0xffffffffu, val, 1);
    if (valid && sl == 0) ew[eg] = val;
    float c1 = (sl == 0 && valid) ? val : 0.f;
    float c2 = c1 * c1;
    c1 += __shfl_xor_sync(0xffffffffu, c1, 8);
    c2 += __shfl_xor_sync(0xffffffffu, c2, 8);
    c1 += __shfl_xor_sync(0xffffffffu, c1, 16);
    c2 += __shfl_xor_sync(0xffffffffu, c2, 16);
    __shared__ float sv[8], sq[8];
    if (lane == 0) { sv[wib] = c1; sq[wib] = c2; }
    __syncthreads();
    if (tid == 0) {
        double s = 0, q = 0;
#pragma unroll
        for (int i = 0; i < 8; i++) { s += (double)sv[i]; q += (double)sq[i]; }
        atomicAdd(sum2 + 0, s);
        atomicAdd(sum2 + 1, q);
    }
}

__global__ void finalize_kernel(const double* __restrict__ sum2, float* __restrict__ ms) {
    double s = sum2[0], q = sum2[1];
    double Ed = (double)EE;
    double mean = s / Ed;
    double var = (q - s * s / Ed) / (Ed - 1.0);
    ms[0] = (float)mean;
    ms[1] = (float)sqrt(1e-4 / var);
}

// ----------------------------------------------------------------------------
// CSR build
// ----------------------------------------------------------------------------
__global__ void count_kernel(const void* __restrict__ ei, int* __restrict__ cnt) {
    int e = blockIdx.x * blockDim.x + threadIdx.x;
    if (e >= EE) return;
    atomicAdd(&cnt[load_edge(ei, 1, e)], 1);
}

__global__ void scan_kernel(const int* __restrict__ cnt, int* __restrict__ off,
                            int* __restrict__ cur) {
    __shared__ int sh[1024];
    const int T = 1024;
    int tid = threadIdx.x;
    const int CH = (NN + T - 1) / T;
    int b0 = tid * CH;
    int loc = 0;
    for (int i = 0; i < CH; i++) {
        int idx = b0 + i;
        if (idx < NN) loc += cnt[idx];
    }
    sh[tid] = loc;
    __syncthreads();
    for (int o = 1; o < T; o <<= 1) {
        int t = (tid >= o) ? sh[tid - o] : 0;
        __syncthreads();
        sh[tid] += t;
        __syncthreads();
    }
    int excl = sh[tid] - loc;
    int run = excl;
    for (int i = 0; i < CH; i++) {
        int idx = b0 + i;
        if (idx < NN) {
            off[idx] = run;
            cur[idx] = run;
            run += cnt[idx];
        }
    }
    if (tid == T - 1) off[NN] = EE;
}

// scatter: build CSR src list AND copy ew into CSR order (kills ceid+ewperm)
__global__ void scatter_kernel(const void* __restrict__ ei, const float* __restrict__ ew,
                               int* __restrict__ cur, int* __restrict__ csrc,
                               float* __restrict__ cew) {
    int e = blockIdx.x * blockDim.x + threadIdx.x;
    if (e >= EE) return;
    int d = load_edge(ei, 1, e);
    int p = atomicAdd(&cur[d], 1);
    csrc[p] = load_edge(ei, 0, e);
    cew[p] = ew[e];
}

// ----------------------------------------------------------------------------
// pos = t2 @ Wp2 + bp2 (K=128, Nout=3). One warp per node.
// ----------------------------------------------------------------------------
__global__ void pos_kernel(const float* __restrict__ t2, const float* __restrict__ Wp2,
                           const float* __restrict__ bp2, float* __restrict__ pos) {
    __shared__ float sw[384];
    for (int i = threadIdx.x; i < 384; i += blockDim.x) sw[i] = Wp2[i];
    __syncthreads();
    int gw = (blockIdx.x * blockDim.x + threadIdx.x) >> 5;
    int lane = threadIdx.x & 31;
    if (gw >= NN) return;
    float4 v = *reinterpret_cast<const float4*>(t2 + (size_t)gw * 128 + lane * 4);
    int k0 = lane * 4;
    float p0 = v.x * sw[k0 * 3 + 0] + v.y * sw[(k0 + 1) * 3 + 0] +
               v.z * sw[(k0 + 2) * 3 + 0] + v.w * sw[(k0 + 3) * 3 + 0];
    float p1 = v.x * sw[k0 * 3 + 1] + v.y * sw[(k0 + 1) * 3 + 1] +
               v.z * sw[(k0 + 2) * 3 + 1] + v.w * sw[(k0 + 3) * 3 + 1];
    float p2 = v.x * sw[k0 * 3 + 2] + v.y * sw[(k0 + 1) * 3 + 2] +
               v.z * sw[(k0 + 2) * 3 + 2] + v.w * sw[(k0 + 3) * 3 + 2];
#pragma unroll
    for (int o = 16; o; o >>= 1) {
        p0 += __shfl_down_sync(0xffffffffu, p0, o);
        p1 += __shfl_down_sync(0xffffffffu, p1, o);
        p2 += __shfl_down_sync(0xffffffffu, p2, o);
    }
    if (lane == 0) {
        pos[gw * 3 + 0] = p0 + __ldg(bp2 + 0);
        pos[gw * 3 + 1] = p1 + __ldg(bp2 + 1);
        pos[gw * 3 + 2] = p2 + __ldg(bp2 + 2);
    }
}

__global__ void pv_kernel(const float* __restrict__ pos, const float* __restrict__ WlB,
                          float* __restrict__ pv) {
    int idx = blockIdx.x * blockDim.x + threadIdx.x;
    if (idx >= NN * 128) return;
    int n = idx >> 7, j = idx & 127;
    float p0 = __ldg(pos + n * 3 + 0);
    float p1 = __ldg(pos + n * 3 + 1);
    float p2 = __ldg(pos + n * 3 + 2);
    pv[idx] = p0 * __ldg(WlB + j) + p1 * __ldg(WlB + 128 + j) + p2 * __ldg(WlB + 256 + j);
}

// ----------------------------------------------------------------------------
// Aggregation: warp per dst node; edge weight affine applied inline.
// agg[n] = max_e ((a[src]-pv[n]) * ((cew[e]-m)*sc+1)); empty -> 0.
// Unrolled x2 with dual accumulators for gather MLP.
// ----------------------------------------------------------------------------
__global__ void agg_kernel(const int* __restrict__ off, const int* __restrict__ csrc,
                           const float* __restrict__ cew, const float* __restrict__ ms,
                           const float* __restrict__ a, const float* __restrict__ pv,
                           float* __restrict__ agg) {
    int gw = (blockIdx.x * blockDim.x + threadIdx.x) >> 5;
    int lane = threadIdx.x & 31;
    if (gw >= NN) return;
    const float m = __ldg(ms + 0), sc = __ldg(ms + 1);
    int beg = __ldg(off + gw), end = __ldg(off + gw + 1);
    float4 pvd = *reinterpret_cast<const float4*>(pv + (size_t)gw * 128 + lane * 4);
    float4 mA = make_float4(-INFINITY, -INFINITY, -INFINITY, -INFINITY);
    float4 mB = mA;
    int e = beg;
    for (; e + 1 < end; e += 2) {
        int s0 = __ldg(csrc + e), s1 = __ldg(csrc + e + 1);
        float w0 = (__ldg(cew + e) - m) * sc + 1.0f;
        float w1 = (__ldg(cew + e + 1) - m) * sc + 1.0f;
        float4 v0 = *reinterpret_cast<const float4*>(a + (size_t)s0 * 128 + lane * 4);
        float4 v1 = *reinterpret_cast<const float4*>(a + (size_t)s1 * 128 + lane * 4);
        mA.x = fmaxf(mA.x, (v0.x - pvd.x) * w0);
        mA.y = fmaxf(mA.y, (v0.y - pvd.y) * w0);
        mA.z = fmaxf(mA.z, (v0.z - pvd.z) * w0);
        mA.w = fmaxf(mA.w, (v0.w - pvd.w) * w0);
        mB.x = fmaxf(mB.x, (v1.x - pvd.x) * w1);
        mB.y = fmaxf(mB.y, (v1.y - pvd.y) * w1);
        mB.z = fmaxf(mB.z, (v1.z - pvd.z) * w1);
        mB.w = fmaxf(mB.w, (v1.w - pvd.w) * w1);
    }
    if (e < end) {
        int s0 = __ldg(csrc + e);
        float w0 = (__ldg(cew + e) - m) * sc + 1.0f;
        float4 v0 = *reinterpret_cast<const float4*>(a + (size_t)s0 * 128 + lane * 4);
        mA.x = fmaxf(mA.x, (v0.x - pvd.x) * w0);
        mA.y = fmaxf(mA.y, (v0.y - pvd.y) * w0);
        mA.z = fmaxf(mA.z, (v0.z - pvd.z) * w0);
        mA.w = fmaxf(mA.w, (v0.w - pvd.w) * w0);
    }
    float4 r;
    if (beg == end) {
        r = make_float4(0.f, 0.f, 0.f, 0.f);
    } else {
        r = make_float4(fmaxf(mA.x, mB.x), fmaxf(mA.y, mB.y),
                        fmaxf(mA.z, mB.z), fmaxf(mA.w, mB.w));
    }
    *reinterpret_cast<float4*>(agg + (size_t)gw * 128 + lane * 4) = r;
}

// ----------------------------------------------------------------------------
// Host launcher
// ----------------------------------------------------------------------------
extern "C" void kernel_launch(void* const* d_in, const int* in_sizes, int n_in,
                              void* d_out, int out_size) {
    const float* x   = (const float*)d_in[0];
    const void*  ei  = d_in[1];
    const float* Wm1 = (const float*)d_in[2];
    const float* Wm2 = (const float*)d_in[4];
    const float* Wm3 = (const float*)d_in[6];
    const float* P0  = (const float*)d_in[8];
    const float* Wi1 = (const float*)d_in[9];
    const float* Wi2 = (const float*)d_in[11];
    const float* Wp1 = (const float*)d_in[13];
    const float* Wp2 = (const float*)d_in[15]; const float* bp2 = (const float*)d_in[16];
    const float* Wl  = (const float*)d_in[17]; const float* bl  = (const float*)d_in[18];
    const float* Wg  = (const float*)d_in[19]; const float* bg  = (const float*)d_in[20];
    const float* Wf  = (const float*)d_in[21]; const float* bf  = (const float*)d_in[22];
    const float* bm1 = (const float*)d_in[3];
    const float* bm2 = (const float*)d_in[5];
    const float* bm3 = (const float*)d_in[7];
    const float* bi1 = (const float*)d_in[10];
    const float* bi2 = (const float*)d_in[12];
    const float* bp1 = (const float*)d_in[14];
    float* out = (float*)d_out;

    float *h1, *h2, *logits, *tp, *xh, *tmp, *a, *pv, *agg, *pos, *ew, *cew, *ms;
    float *btm1, *btm2, *btm3, *pt, *bti1, *bti2, *btp1, *btlA, *btg, *btf;
    int *cnt, *off, *cur, *csrc;
    double* sum2;
    cudaGetSymbolAddress((void**)&h1, g_h1);
    cudaGetSymbolAddress((void**)&h2, g_h2);
    cudaGetSymbolAddress((void**)&logits, g_logits);
    cudaGetSymbolAddress((void**)&tp, g_tp);
    cudaGetSymbolAddress((void**)&xh, g_xh);
    cudaGetSymbolAddress((void**)&tmp, g_tmp);
    cudaGetSymbolAddress((void**)&a, g_a);
    cudaGetSymbolAddress((void**)&pv, g_pv);
    cudaGetSymbolAddress((void**)&agg, g_agg);
    cudaGetSymbolAddress((void**)&pos, g_pos);
    cudaGetSymbolAddress((void**)&ew, g_ew);
    cudaGetSymbolAddress((void**)&cew, g_cew);
    cudaGetSymbolAddress((void**)&ms, g_ms);
    cudaGetSymbolAddress((void**)&cnt, g_cnt);
    cudaGetSymbolAddress((void**)&off, g_off);
    cudaGetSymbolAddress((void**)&cur, g_cur);
    cudaGetSymbolAddress((void**)&csrc, g_csrc);
    cudaGetSymbolAddress((void**)&sum2, g_sum2);
    cudaGetSymbolAddress((void**)&btm1, g_btm1);
    cudaGetSymbolAddress((void**)&btm2, g_btm2);
    cudaGetSymbolAddress((void**)&btm3, g_btm3);
    cudaGetSymbolAddress((void**)&pt, g_pt);
    cudaGetSymbolAddress((void**)&bti1, g_bti1);
    cudaGetSymbolAddress((void**)&bti2, g_bti2);
    cudaGetSymbolAddress((void**)&btp1, g_btp1);
    cudaGetSymbolAddress((void**)&btlA, g_btlA);
    cudaGetSymbolAddress((void**)&btg, g_btg);
    cudaGetSymbolAddress((void**)&btf, g_btf);

    const int GM = (NN + 127) / 128;  // 782
    const int SM128 = 2 * 40 * (128 + 128) * 4;  // 81920
    const int SM64  = 2 * 40 * (128 + 64) * 4;   // 61440

    cudaFuncSetAttribute(mma_gemm<128, EPI_BIAS | EPI_RELU>,
                         cudaFuncAttributeMaxDynamicSharedMemorySize, SM128);
    cudaFuncSetAttribute(mma_gemm<128, EPI_BIAS>,
                         cudaFuncAttributeMaxDynamicSharedMemorySize, SM128);
    cudaFuncSetAttribute(mma_gemm<128, EPI_BIAS | EPI_ADDC>,
                         cudaFuncAttributeMaxDynamicSharedMemorySize, SM128);
    cudaFuncSetAttribute(mma_gemm<64, EPI_BIAS | EPI_RELU>,
                         cudaFuncAttributeMaxDynamicSharedMemorySize, SM64);
    cudaFuncSetAttribute(mma_gemm<64, EPI_BIAS>,
                         cudaFuncAttributeMaxDynamicSharedMemorySize, SM64);
    cudaFuncSetAttribute(mma_gemm<64, 0>,
                         cudaFuncAttributeMaxDynamicSharedMemorySize, SM64);

    // fused prep (transposes + parsing + dtype detect) + zeroing
    prep_kernel<<<769, 256>>>((const ull*)ei, Wm1, Wm2, Wm3, P0, Wi1, Wi2, Wp1, Wl, Wg, Wf);
    cudaMemsetAsync(cnt, 0, NN * sizeof(int));
    cudaMemsetAsync(sum2, 0, 2 * sizeof(double));

    // CSR counts (needs is64 from prep)
    count_kernel<<<6250, 256>>>(ei, cnt);
    scan_kernel<<<1, 1024>>>(cnt, off, cur);

    // pseudo-MLP chain
    mma_gemm<128, EPI_BIAS | EPI_RELU><<<dim3(GM, 4), 256, SM128>>>(x, btm1, bm1, nullptr, h1, NN, 128, 512);
    mma_gemm<64, EPI_BIAS | EPI_RELU><<<dim3(GM, 1), 256, SM64>>>(h1, btm2, bm2, nullptr, h2, NN, 512, 64);
    mma_gemm<64, EPI_BIAS><<<dim3(GM, 1), 256, SM64>>>(h2, btm3, bm3, nullptr, logits, NN, 64, 64);
    mma_gemm<64, 0><<<dim3(GM, 1), 256, SM64>>>(logits, pt, nullptr, nullptr, tp, NN, 64, 64);

    // edge weights (orig order) + CSR scatter with fused ew permute
    ew_kernel<<<50000, 256>>>(ei, logits, tp, ew, sum2);
    finalize_kernel<<<1, 1>>>(sum2, ms);
    scatter_kernel<<<6250, 256>>>(ei, ew, cur, csrc, cew);

    // initial MLP
    mma_gemm<128, EPI_BIAS | EPI_RELU><<<dim3(GM, 1), 256, SM128>>>(x, bti1, bi1, nullptr, tmp, NN, 128, 128);
    mma_gemm<128, EPI_BIAS><<<dim3(GM, 1), 256, SM128>>>(tmp, bti2, bi2, nullptr, xh, NN, 128, 128);

    // pos / pv
    mma_gemm<128, EPI_BIAS | EPI_RELU><<<dim3(GM, 1), 256, SM128>>>(xh, btp1, bp1, nullptr, tmp, NN, 128, 128);
    pos_kernel<<<12500, 256>>>(tmp, Wp2, bp2, pos);
    pv_kernel<<<50000, 256>>>(pos, Wl + 128 * 128, pv);

    // 2 PointNetConv layers (shared weights)
    for (int layer = 0; layer < 2; layer++) {
        mma_gemm<128, EPI_BIAS | EPI_ADDC><<<dim3(GM, 1), 256, SM128>>>(xh, btlA, bl, pv, a, NN, 128, 128);
        agg_kernel<<<12500, 256>>>(off, csrc, cew, ms, a, pv, agg);
        mma_gemm<128, EPI_BIAS | EPI_RELU><<<dim3(GM, 1), 256, SM128>>>(agg, btg, bg, nullptr, xh, NN, 128, 128);
    }

    // out = xh @ Wf + bf
    mma_gemm<64, EPI_BIAS><<<dim3(GM, 1), 256, SM64>>>(xh, btf, bf, nullptr, out, NN, 128, 64);
}